// round 3
// baseline (speedup 1.0000x reference)
#include <cuda_runtime.h>

// Fixed shapes: B=2, H=8, S=256, d=64
#define NB 2
#define NH 8
#define NS 256
#define ND 64
#define PER_B (NH*NS*ND)      // 131072 floats per batch in Q/V
#define OUT_HALF (NB*PER_B)   // 262144 floats: attn offset (context first, attn second)

#define GRID_BLOCKS 128

// W[b][u][e] = sum_{r=0..7} Q[b*131072 + u*512 + r*64 + e] * V[same], u in [0,256)
// g_CP[b][c][i][e] = inclusive prefix of W over i within chunk c (u = c*64+i).
__device__ float    g_CP[NB][4][64][64];
__device__ unsigned g_arrive;   // monotonic ticket counter (never reset)

__global__ void __launch_bounds__(256) k_fused(const float* __restrict__ Q,
                                               const float* __restrict__ V,
                                               float* __restrict__ out) {
    int tid = threadIdx.x;
    int blk = blockIdx.x;

    __shared__ float Wsm[64][8];   // [u_local][e_local]

    // ---------------- Phase 1: chunk prefixes (blocks 0..63) ----------------
    if (blk < 64) {
        int b   = blk >> 5;        // 0..1
        int c   = (blk >> 3) & 3;  // 0..3
        int eq8 = blk & 7;         // which 8-wide e slice

        if (tid < 128) {
            int ul  = tid >> 1;    // 0..63
            int col = tid & 1;     // which float4 column of the 8-e slice

            const float4* Q4 = reinterpret_cast<const float4*>(Q) + b * (PER_B / 4);
            const float4* V4 = reinterpret_cast<const float4*>(V) + b * (PER_B / 4);

            // float4 index of (u*512 + r*64 + eq8*8 + col*4)
            int base4 = (c * 64 + ul) * 128 + eq8 * 2 + col;

            float4 acc = make_float4(0.f, 0.f, 0.f, 0.f);
            #pragma unroll
            for (int r = 0; r < 8; r++) {
                float4 q = Q4[base4 + r * 16];
                float4 v = V4[base4 + r * 16];
                acc.x = fmaf(q.x, v.x, acc.x);
                acc.y = fmaf(q.y, v.y, acc.y);
                acc.z = fmaf(q.z, v.z, acc.z);
                acc.w = fmaf(q.w, v.w, acc.w);
            }
            *reinterpret_cast<float4*>(&Wsm[ul][col * 4]) = acc;
        }
        __syncthreads();

        // Serial inclusive prefix along u for the 8 e-columns of this slice.
        if (tid < 8) {
            float a = 0.f;
            #pragma unroll
            for (int i = 0; i < 64; i++) {
                a += Wsm[i][tid];
                g_CP[b][c][i][eq8 * 8 + tid] = a;
            }
        }
    }

    // ---------------- Grid barrier (ticket-based, self-consistent across replays) ----
    __threadfence();
    if (tid == 0) {
        unsigned v = atomicAdd(&g_arrive, 1u);
        unsigned target = (v - (v & (GRID_BLOCKS - 1))) + GRID_BLOCKS;
        volatile unsigned* p = &g_arrive;
        while ((int)(*p - target) < 0) { }
        __threadfence();
    }
    __syncthreads();

    // ---------------- Phase 2: softmax + outputs (all 128 blocks) ----------------
    int warp = tid >> 5;
    int lane = tid & 31;
    int sub  = lane >> 4;       // row within half-warp pair
    int l    = lane & 15;       // e-slot: covers e = 4l .. 4l+3

    const float4* CP4 = reinterpret_cast<const float4*>(g_CP);
    int rowBase = blk * 32 + warp * 4 + sub;

    #pragma unroll
    for (int it = 0; it < 2; it++) {
        int row = rowBase + it * 2;          // 0..4095 = ((b*8+h)*256+s)
        int b = row >> 11;
        int h = (row >> 8) & 7;
        int s = row & 255;

        // Circular window [base, base+63] mod 512 intersected with [0,256):
        // always empty or one interval.
        int base = (((s & 7) << 6) + (h << 5) + (s >> 3) + 256) & 511;

        float4 sc = make_float4(0.f, 0.f, 0.f, 0.f);
        if (base < 256 || base > 448) {
            int lo, hi;
            if (base < 256) { lo = base; hi = min(base + 63, 255); }
            else            { lo = 0;    hi = base - 449; }          // wrap
            int c0 = lo >> 6, c1 = hi >> 6;   // c1 == c0 or c0+1
            int i0 = lo & 63, i1 = hi & 63;

            // float4 index of g_CP[b][c][i][4l] = ((b*4+c)*64 + i)*16 + l
            float4 hiV = CP4[((b * 4 + c1) * 64 + i1) * 16 + l];
            float4 loV = make_float4(0.f, 0.f, 0.f, 0.f);
            if (i0 > 0) loV = CP4[((b * 4 + c0) * 64 + (i0 - 1)) * 16 + l];

            if (c0 == c1) {
                sc.x = hiV.x - loV.x;
                sc.y = hiV.y - loV.y;
                sc.z = hiV.z - loV.z;
                sc.w = hiV.w - loV.w;
            } else {
                float4 T = CP4[((b * 4 + c0) * 64 + 63) * 16 + l]; // chunk total
                sc.x = (T.x - loV.x) + hiV.x;
                sc.y = (T.y - loV.y) + hiV.y;
                sc.z = (T.z - loV.z) + hiV.z;
                sc.w = (T.w - loV.w) + hiV.w;
            }
        }

        // softmax over 64 e's: 4 per lane, reduce across the 16-lane half-warp.
        float m = fmaxf(fmaxf(sc.x, sc.y), fmaxf(sc.z, sc.w));
        #pragma unroll
        for (int d_ = 8; d_ > 0; d_ >>= 1)
            m = fmaxf(m, __shfl_xor_sync(0xffffffffu, m, d_));

        float e0 = __expf(sc.x - m);
        float e1 = __expf(sc.y - m);
        float e2 = __expf(sc.z - m);
        float e3 = __expf(sc.w - m);
        float ssum = (e0 + e1) + (e2 + e3);
        #pragma unroll
        for (int d_ = 8; d_ > 0; d_ >>= 1)
            ssum += __shfl_xor_sync(0xffffffffu, ssum, d_);
        float inv = __frcp_rn(ssum);

        float4 a = make_float4(e0 * inv, e1 * inv, e2 * inv, e3 * inv);

        int off4 = row * 16 + l;   // float4 index into a 64-float row
        float4 v = reinterpret_cast<const float4*>(V)[off4];

        reinterpret_cast<float4*>(out)[(OUT_HALF / 4) + off4] = a;        // attn
        reinterpret_cast<float4*>(out)[off4] =
            make_float4(a.x * v.x, a.y * v.y, a.z * v.z, a.w * v.w);      // context
    }
}

extern "C" void kernel_launch(void* const* d_in, const int* in_sizes, int n_in,
                              void* d_out, int out_size) {
    const float* Q = (const float*)d_in[0];
    // d_in[1] (K) is genuinely unused by the reference computation.
    const float* V = (const float*)d_in[2];
    float* out = (float*)d_out;

    k_fused<<<GRID_BLOCKS, 256>>>(Q, V, out);
}

// round 5
// speedup vs baseline: 1.2394x; 1.2394x over previous
#include <cuda_runtime.h>

// Fixed shapes: B=2, H=8, S=256, d=64
#define NB 2
#define NH 8
#define NS 256
#define ND 64
#define PER_B (NH*NS*ND)      // 131072 floats per batch in Q/V
#define OUT_HALF (NB*PER_B)   // 262144 floats: attn offset (context first, attn second)

// W[b][u][e] = sum_{r=0..7} Q[b*131072 + u*512 + r*64 + e] * V[same], u in [0,256)
// g_CP[b][c][i][e] = inclusive prefix of W over i within chunk c (u = c*64+i).
// Chunk total == g_CP[b][c][63][e].
__device__ float g_CP[NB][4][64][64];

// 64 blocks: blk = b*32 + c*8 + eq8 (eq8 = 8-wide e slice). 256 threads:
// tid = ul*4 + col*2 + rh  (ul: u_local 0..63, col: float4 within slice, rh: r half)
__global__ void __launch_bounds__(256) k_chunk_prefix(const float* __restrict__ Q,
                                                      const float* __restrict__ V) {
    int blk = blockIdx.x;
    int b   = blk >> 5;
    int c   = (blk >> 3) & 3;
    int eq8 = blk & 7;

    __shared__ float Wsm[64][8];

    int tid = threadIdx.x;
    int ul  = tid >> 2;
    int col = (tid >> 1) & 1;
    int rh  = tid & 1;

    const float4* Q4 = reinterpret_cast<const float4*>(Q) + b * (PER_B / 4);
    const float4* V4 = reinterpret_cast<const float4*>(V) + b * (PER_B / 4);

    // float4 index of (u*512 + r*64 + eq8*8 + col*4)
    int base4 = (c * 64 + ul) * 128 + eq8 * 2 + col + rh * 4 * 16;

    float4 acc = make_float4(0.f, 0.f, 0.f, 0.f);
    #pragma unroll
    for (int r = 0; r < 4; r++) {
        float4 q = Q4[base4 + r * 16];
        float4 v = V4[base4 + r * 16];
        acc.x = fmaf(q.x, v.x, acc.x);
        acc.y = fmaf(q.y, v.y, acc.y);
        acc.z = fmaf(q.z, v.z, acc.z);
        acc.w = fmaf(q.w, v.w, acc.w);
    }
    // combine the two r-halves (partner differs only in bit 0 of lane)
    acc.x += __shfl_xor_sync(0xffffffffu, acc.x, 1);
    acc.y += __shfl_xor_sync(0xffffffffu, acc.y, 1);
    acc.z += __shfl_xor_sync(0xffffffffu, acc.z, 1);
    acc.w += __shfl_xor_sync(0xffffffffu, acc.w, 1);
    if (rh == 0)
        *reinterpret_cast<float4*>(&Wsm[ul][col * 4]) = acc;
    __syncthreads();

    // Serial inclusive prefix along u for the 8 e-columns of this slice.
    if (tid < 8) {
        float a = 0.f;
        #pragma unroll
        for (int i = 0; i < 64; i++) {
            a += Wsm[i][tid];
            g_CP[b][c][i][eq8 * 8 + tid] = a;
        }
    }

    // Release this CTA's CP stores to the dependent grid.
    cudaTriggerProgrammaticLaunchCompletion();
}

// Grid 256 blocks x 256 threads. Each warp handles 2 rows (16 lanes/row),
// each lane covers 4 consecutive e's via float4.
__global__ void __launch_bounds__(256) k_attn(const float* __restrict__ V,
                                              float* __restrict__ out) {
    int warp = threadIdx.x >> 5;
    int lane = threadIdx.x & 31;
    int sub  = lane >> 4;
    int l    = lane & 15;       // e-slot: covers e = 4l .. 4l+3

    int row = blockIdx.x * 16 + warp * 2 + sub;   // ((b*8+h)*256+s)
    int b = row >> 11;
    int h = (row >> 8) & 7;
    int s = row & 255;

    // Circular window [base, base+63] mod 512, intersected with [0,256).
    int base = (((s & 7) << 6) + (h << 5) + (s >> 3) + 256) & 511;

    // Pure-input load: safe before the dependency sync, overlaps the producer.
    int off4 = row * 16 + l;
    float4 v = reinterpret_cast<const float4*>(V)[off4];

    // Acquire the producer's CP writes.
    cudaGridDependencySynchronize();

    const float4* CP4 = reinterpret_cast<const float4*>(g_CP);
    float4 sc = make_float4(0.f, 0.f, 0.f, 0.f);

    if (base < 256 || base > 448) {
        int lo, hi;
        if (base < 256) { lo = base; hi = min(base + 63, 255); }
        else            { lo = 0;    hi = base - 449; }          // wrap
        int c0 = lo >> 6, c1 = hi >> 6;   // c1 == c0 or c0+1
        int i0 = lo & 63, i1 = hi & 63;

        // float4 index of g_CP[b][c][i][4l] = ((b*4+c)*64 + i)*16 + l
        float4 hiV = CP4[((b * 4 + c1) * 64 + i1) * 16 + l];
        float4 loV = make_float4(0.f, 0.f, 0.f, 0.f);
        if (i0 > 0) loV = CP4[((b * 4 + c0) * 64 + (i0 - 1)) * 16 + l];

        if (c0 == c1) {
            sc.x = hiV.x - loV.x;
            sc.y = hiV.y - loV.y;
            sc.z = hiV.z - loV.z;
            sc.w = hiV.w - loV.w;
        } else {
            float4 T = CP4[((b * 4 + c0) * 64 + 63) * 16 + l];   // chunk total
            sc.x = (T.x - loV.x) + hiV.x;
            sc.y = (T.y - loV.y) + hiV.y;
            sc.z = (T.z - loV.z) + hiV.z;
            sc.w = (T.w - loV.w) + hiV.w;
        }
    }

    // softmax over 64 e's: 4 per lane, reduce across the 16-lane half-warp.
    float m = fmaxf(fmaxf(sc.x, sc.y), fmaxf(sc.z, sc.w));
    #pragma unroll
    for (int d_ = 8; d_ > 0; d_ >>= 1)
        m = fmaxf(m, __shfl_xor_sync(0xffffffffu, m, d_));

    float e0 = __expf(sc.x - m);
    float e1 = __expf(sc.y - m);
    float e2 = __expf(sc.z - m);
    float e3 = __expf(sc.w - m);
    float ssum = (e0 + e1) + (e2 + e3);
    #pragma unroll
    for (int d_ = 8; d_ > 0; d_ >>= 1)
        ssum += __shfl_xor_sync(0xffffffffu, ssum, d_);
    float inv = __frcp_rn(ssum);

    float4 a = make_float4(e0 * inv, e1 * inv, e2 * inv, e3 * inv);

    reinterpret_cast<float4*>(out)[(OUT_HALF / 4) + off4] = a;         // attn
    reinterpret_cast<float4*>(out)[off4] =
        make_float4(a.x * v.x, a.y * v.y, a.z * v.z, a.w * v.w);       // context
}

extern "C" void kernel_launch(void* const* d_in, const int* in_sizes, int n_in,
                              void* d_out, int out_size) {
    const float* Q = (const float*)d_in[0];
    // d_in[1] (K) is genuinely unused by the reference computation.
    const float* V = (const float*)d_in[2];
    float* out = (float*)d_out;

    cudaLaunchConfig_t cfg1 = {};
    cfg1.gridDim  = dim3(64);
    cfg1.blockDim = dim3(256);
    cfg1.stream   = 0;
    cudaLaunchKernelEx(&cfg1, k_chunk_prefix, Q, V);

    cudaLaunchAttribute attr;
    attr.id = cudaLaunchAttributeProgrammaticStreamSerialization;
    attr.val.programmaticStreamSerializationAllowed = 1;

    cudaLaunchConfig_t cfg2 = {};
    cfg2.gridDim  = dim3(256);
    cfg2.blockDim = dim3(256);
    cfg2.stream   = 0;
    cfg2.attrs    = &attr;
    cfg2.numAttrs = 1;
    cudaLaunchKernelEx(&cfg2, k_attn, V, out);
}